// round 9
// baseline (speedup 1.0000x reference)
#include <cuda_runtime.h>
#include <cuda_bf16.h>
#include <math.h>
#include <stdint.h>

typedef __nv_bfloat16 bf16;

#define Dq 1024
#define Pq 128
#define Bq 4096
#define Nq 8192
#define Cq 1000

// ---------------- scratch (static device memory; no allocations) -----------
__device__ bf16  g_xb [Nq * Dq];
__device__ bf16  g_W1b[Pq * Dq];
__device__ bf16  g_W2b[Pq * Pq];
__device__ bf16  g_W3b[3 * Dq * Pq];
__device__ bf16  g_Wpb[Dq * Dq];
__device__ bf16  g_H1b[Nq * Pq];
__device__ bf16  g_H2b[Nq * Pq];
__device__ bf16  g_Qb [Bq * Dq];
__device__ bf16  g_Kb [Nq * Dq];
__device__ bf16  g_Vb [Nq * Dq];
__device__ bf16  g_Sb [(size_t)Bq * Nq];
__device__ bf16  g_AVb[Bq * Dq];
__device__ float g_F  [Bq * Dq];
__device__ float g_G  [Bq * Dq];
__device__ bf16  g_Ap [(size_t)Bq * 3 * Dq];
__device__ bf16  g_Bp [(size_t)Cq * 3 * Dq];

// ---------------- helpers ---------------------------------------------------
__device__ __forceinline__ uint32_t s2u(const void* p) {
    uint32_t a;
    asm("{ .reg .u64 t; cvta.to.shared.u64 t, %1; cvt.u32.u64 %0, t; }"
        : "=r"(a) : "l"(p));
    return a;
}
__device__ __forceinline__ void ldmx4(uint32_t* r, uint32_t a) {
    asm volatile("ldmatrix.sync.aligned.m8n8.x4.shared.b16 {%0,%1,%2,%3}, [%4];"
                 : "=r"(r[0]), "=r"(r[1]), "=r"(r[2]), "=r"(r[3]) : "r"(a));
}
__device__ __forceinline__ void ldmx4t(uint32_t* r, uint32_t a) {
    asm volatile("ldmatrix.sync.aligned.m8n8.x4.trans.shared.b16 {%0,%1,%2,%3}, [%4];"
                 : "=r"(r[0]), "=r"(r[1]), "=r"(r[2]), "=r"(r[3]) : "r"(a));
}
__device__ __forceinline__ void mma16816(float* c, const uint32_t* a, const uint32_t* b) {
    asm volatile("mma.sync.aligned.m16n8k16.row.col.f32.bf16.bf16.f32 "
                 "{%0,%1,%2,%3}, {%4,%5,%6,%7}, {%8,%9}, {%0,%1,%2,%3};"
                 : "+f"(c[0]), "+f"(c[1]), "+f"(c[2]), "+f"(c[3])
                 : "r"(a[0]), "r"(a[1]), "r"(a[2]), "r"(a[3]),
                   "r"(b[0]), "r"(b[1]));
}
__device__ __forceinline__ void cp16(uint32_t dst, const void* src) {
    asm volatile("cp.async.cg.shared.global [%0], [%1], 16;"
                 :: "r"(dst), "l"(src));
}
__device__ __forceinline__ void cp16z(uint32_t dst, const void* src, int sz) {
    asm volatile("cp.async.cg.shared.global [%0], [%1], 16, %2;"
                 :: "r"(dst), "l"(src), "r"(sz));
}
__device__ __forceinline__ void cp_commit() {
    asm volatile("cp.async.commit_group;" ::: "memory");
}

// ---------------- mma.sync GEMM -----------------------------------
// TRANSB=true : C(MxN) = A(MxK) @ B(NxK)^T   (B row-major N x K)
// TRANSB=false: C(MxN) = A(MxK) @ B(KxN)     (B row-major K x N)
// BM=128, BN in {128,256}, BK=32. Always 256 threads = 8 warps (2 x 4),
// warp tile 64 x (BN/4). 4-stage cp.async pipeline.
#define SROW 80                         // A / NT-B smem row stride bytes
#define ATILE_B (128 * SROW)            // 10240
#define NSTAGE  4

#define MODE_SMUL   0  // bf16 out = acc*scale
#define MODE_BNRELU 1  // bf16 out = relu(bn(acc+bias))
#define MODE_QKV    2  // grouped scatter (W3 rows pre-permuted), null dst skipped
#define MODE_RESID  3  // f32 out = acc + bias[c] + resid[row,c]
#define MODE_LS     4  // f32 out = acc * exp(*lsp), ragged-N guarded

template <int BN, bool TRANSB>
__device__ __forceinline__ void stage_load(const bf16* __restrict__ A,
                                           const bf16* __restrict__ Bm,
                                           int N_, int K_, int m0, int n0, int k0,
                                           uint32_t sbase, int tid)
{
    // A: 512 16B chunks (128 rows x 4)
#pragma unroll
    for (int i = tid; i < 512; i += 256) {
        const int row = i >> 2, ch = i & 3;
        cp16(sbase + row * SROW + ch * 16,
             A + (size_t)(m0 + row) * K_ + k0 + ch * 8);
    }
    if (TRANSB) {
        // B tile: BN rows (n) x 32 k, ragged-N guarded
#pragma unroll
        for (int i = tid; i < 4 * BN; i += 256) {
            const int row = i >> 2, ch = i & 3;
            const int grow = n0 + row;
            const int v = (grow < N_);
            cp16z(sbase + ATILE_B + row * SROW + ch * 16,
                  Bm + (size_t)(v ? grow : 0) * K_ + k0 + ch * 8, v ? 16 : 0);
        }
    } else {
        // B tile: 32 rows (k) x BN n-cols; requires N_ % BN == 0
        constexpr int CPR = BN / 8;          // 16B chunks per row
        constexpr int BROW = 2 * BN + 16;
#pragma unroll
        for (int i = tid; i < 32 * CPR; i += 256) {
            const int kk = i / CPR, ch = i % CPR;
            cp16(sbase + ATILE_B + kk * BROW + ch * 16,
                 Bm + (size_t)(k0 + kk) * N_ + n0 + ch * 8);
        }
    }
}

template <int BN, bool TRANSB>
__device__ __forceinline__ void compute_stage(uint32_t sbase, int lane,
                                              int wm, int wn,
                                              float acc[4][BN / 32][4])
{
    constexpr int TN = BN / 32;          // n-tiles (8 cols) per warp
    constexpr int WN = BN / 4;           // cols per warp
    constexpr int BROW = 2 * BN + 16;
    const uint32_t aBase = sbase + (wm * 64 + (lane & 15)) * SROW + (lane >> 4) * 16;
    uint32_t bBase;
    if (TRANSB) {
        bBase = sbase + ATILE_B +
                (wn * WN + ((lane >> 4) << 3) + (lane & 7)) * SROW +
                (((lane >> 3) & 1) << 4);
    } else {
        bBase = sbase + ATILE_B +
                ((lane & 7) + (((lane >> 3) & 1) << 3)) * BROW +
                (wn * WN + (lane >> 4) * 8) * 2;
    }
#pragma unroll
    for (int kh = 0; kh < 2; ++kh) {
        uint32_t af[4][4];
#pragma unroll
        for (int tm = 0; tm < 4; ++tm)
            ldmx4(af[tm], aBase + tm * 16 * SROW + kh * 32);
        uint32_t bfr[TN][2];
#pragma unroll
        for (int tp = 0; tp < TN / 2; ++tp) {
            uint32_t r[4];
            if (TRANSB) ldmx4(r, bBase + tp * 16 * SROW + kh * 32);
            else        ldmx4t(r, bBase + kh * 16 * BROW + tp * 32);
            bfr[2 * tp][0] = r[0];  bfr[2 * tp][1] = r[1];
            bfr[2 * tp + 1][0] = r[2]; bfr[2 * tp + 1][1] = r[3];
        }
#pragma unroll
        for (int tm = 0; tm < 4; ++tm)
#pragma unroll
            for (int tn = 0; tn < TN; ++tn)
                mma16816(acc[tm][tn], af[tm], bfr[tn]);
    }
}

template <int BN, bool TRANSB>
__global__ __launch_bounds__(256, 1)
void tc_gemm(const bf16* __restrict__ A, const bf16* __restrict__ Bm,
             int M, int N, int K, int mode, float scale,
             const float* __restrict__ bias, const float* __restrict__ gam,
             const float* __restrict__ bet, const float* __restrict__ mean,
             const float* __restrict__ var, const float* __restrict__ resid,
             const float* __restrict__ lsp,
             void* __restrict__ Cout,
             bf16* __restrict__ qo, bf16* __restrict__ ko, bf16* __restrict__ vo)
{
    constexpr int TN = BN / 32;
    constexpr int WN = BN / 4;
    constexpr int BSTAGE = TRANSB ? BN * SROW : 32 * (2 * BN + 16);
    constexpr int STAGE = ATILE_B + BSTAGE;
    extern __shared__ char smem[];
    const uint32_t sb = s2u(smem);
    const int tid  = threadIdx.x;
    const int lane = tid & 31;
    const int wid  = tid >> 5;
    const int wm = wid >> 2, wn = wid & 3;
    const int m0 = blockIdx.y * 128;
    const int n0 = blockIdx.x * BN;
    const int NC = K >> 5;

    float acc[4][TN][4];
#pragma unroll
    for (int a = 0; a < 4; ++a)
#pragma unroll
        for (int b = 0; b < TN; ++b)
#pragma unroll
            for (int c = 0; c < 4; ++c) acc[a][b][c] = 0.f;

    // prologue: prefetch NSTAGE-1 stages (NC >= 4 in all our calls)
#pragma unroll
    for (int s = 0; s < NSTAGE - 1; ++s) {
        stage_load<BN, TRANSB>(A, Bm, N, K, m0, n0, s * 32, sb + s * STAGE, tid);
        cp_commit();
    }

    for (int i = 0; i < NC; ++i) {
        asm volatile("cp.async.wait_group %0;" :: "n"(NSTAGE - 2) : "memory");
        __syncthreads();
        compute_stage<BN, TRANSB>(sb + (i % NSTAGE) * STAGE, lane, wm, wn, acc);
        if (i + NSTAGE - 1 < NC)
            stage_load<BN, TRANSB>(A, Bm, N, K, m0, n0, (i + NSTAGE - 1) * 32,
                                   sb + ((i + NSTAGE - 1) % NSTAGE) * STAGE, tid);
        cp_commit();
    }
    asm volatile("cp.async.wait_group 0;" ::: "memory");

    // ---------------- epilogue ---------------------------------------------
    const float lsv = (mode == MODE_LS) ? __expf(lsp[0]) : 1.f;

#pragma unroll
    for (int tm = 0; tm < 4; ++tm) {
#pragma unroll
        for (int tn = 0; tn < TN; ++tn) {
            const int r0 = m0 + wm * 64 + tm * 16 + (lane >> 2);
            const int c0 = n0 + wn * WN + tn * 8 + 2 * (lane & 3);
#pragma unroll
            for (int h = 0; h < 2; ++h) {
                const int row = r0 + 8 * h;
                const float f0 = acc[tm][tn][2 * h];
                const float f1 = acc[tm][tn][2 * h + 1];
                if (mode == MODE_SMUL) {
                    __nv_bfloat162 p = __floats2bfloat162_rn(f0 * scale, f1 * scale);
                    *reinterpret_cast<__nv_bfloat162*>(
                        (bf16*)Cout + (size_t)row * N + c0) = p;
                } else if (mode == MODE_BNRELU) {
                    float x0 = f0 + bias[c0];
                    x0 = (x0 - mean[c0]) * rsqrtf(var[c0] + 1e-5f) * gam[c0] + bet[c0];
                    float x1 = f1 + bias[c0 + 1];
                    x1 = (x1 - mean[c0 + 1]) * rsqrtf(var[c0 + 1] + 1e-5f) * gam[c0 + 1]
                         + bet[c0 + 1];
                    __nv_bfloat162 p = __floats2bfloat162_rn(fmaxf(x0, 0.f),
                                                             fmaxf(x1, 0.f));
                    *reinterpret_cast<__nv_bfloat162*>(
                        (bf16*)Cout + (size_t)row * N + c0) = p;
                } else if (mode == MODE_QKV) {
                    // cols pre-grouped: [0,1024) q, [1024,2048) k, [2048,3072) v
                    const int g = c0 >> 10;
                    const int d = c0 & 1023;
                    bf16* dst = (g == 0) ? qo : ((g == 1) ? ko : vo);
                    if (dst) {
                        const float hv0 = f0 + bias[3 * d + g];
                        const float hv1 = f1 + bias[3 * (d + 1) + g];
                        __nv_bfloat162 p = __floats2bfloat162_rn(hv0, hv1);
                        *reinterpret_cast<__nv_bfloat162*>(
                            dst + (size_t)row * 1024 + d) = p;
                    }
                } else if (mode == MODE_RESID) {
                    float* Cf = (float*)Cout + (size_t)row * N + c0;
                    const float2 rv = *reinterpret_cast<const float2*>(
                        resid + (size_t)row * N + c0);
                    float2 o;
                    o.x = f0 + bias[c0] + rv.x;
                    o.y = f1 + bias[c0 + 1] + rv.y;
                    *reinterpret_cast<float2*>(Cf) = o;
                } else { // MODE_LS (N ragged; N even so pair-guard ok)
                    if (c0 < N) {
                        float* Cf = (float*)Cout + (size_t)row * N + c0;
                        Cf[0] = f0 * lsv;
                        Cf[1] = f1 * lsv;
                    }
                }
            }
        }
    }
}

#define SMEM_NT128 (NSTAGE * (ATILE_B + 128 * SROW))           // 81920
#define SMEM_NT256 (NSTAGE * (ATILE_B + 256 * SROW))           // 122880
#define SMEM_NN256 (NSTAGE * (ATILE_B + 32 * (2 * 256 + 16)))  // 108544

// ---------------- small kernels --------------------------------------------
__global__ void f2b_kernel(const float* __restrict__ in, bf16* __restrict__ out, int n)
{
    const int i = (blockIdx.x * blockDim.x + threadIdx.x) * 4;
    if (i < n) {
        const float4 v = *reinterpret_cast<const float4*>(in + i);
        __nv_bfloat162 a = __floats2bfloat162_rn(v.x, v.y);
        __nv_bfloat162 b = __floats2bfloat162_rn(v.z, v.w);
        uint2 pk;
        pk.x = *reinterpret_cast<uint32_t*>(&a);
        pk.y = *reinterpret_cast<uint32_t*>(&b);
        *reinterpret_cast<uint2*>(out + i) = pk;
    }
}

// W3 (3072,128) -> bf16 with rows permuted: out row g*1024+d = orig row 3d+g
__global__ void f2bW3_kernel(const float* __restrict__ in, bf16* __restrict__ out)
{
    const int idx = blockIdx.x * blockDim.x + threadIdx.x;
    if (idx >= 3072 * 128) return;
    const int rp = idx >> 7, c = idx & 127;
    const int g = rp >> 10, d = rp & 1023;
    out[idx] = __float2bfloat16(in[(3 * d + g) * 128 + c]);
}

// in-place row softmax over 8192 bf16 cols
__global__ void softmax_bf16(bf16* __restrict__ S)
{
    bf16* p = S + (size_t)blockIdx.x * 8192;
    const int tid = threadIdx.x;
    const int lane = tid & 31, w = tid >> 5;

    float v[32];
    float mx = -3.4e38f;
#pragma unroll
    for (int i = 0; i < 16; ++i) {
        const __nv_bfloat162 h2 = *reinterpret_cast<const __nv_bfloat162*>(
            p + tid * 2 + (i << 9));
        const float2 f2 = __bfloat1622float2(h2);
        v[2 * i] = f2.x; v[2 * i + 1] = f2.y;
        mx = fmaxf(mx, fmaxf(f2.x, f2.y));
    }
    __shared__ float shm[8], shs[8];
#pragma unroll
    for (int o = 16; o > 0; o >>= 1) mx = fmaxf(mx, __shfl_xor_sync(0xffffffffu, mx, o));
    if (lane == 0) shm[w] = mx;
    __syncthreads();
    if (tid == 0) {
        float m = shm[0];
#pragma unroll
        for (int i = 1; i < 8; ++i) m = fmaxf(m, shm[i]);
        shm[0] = m;
    }
    __syncthreads();
    mx = shm[0];

    float s = 0.f;
#pragma unroll
    for (int i = 0; i < 32; ++i) { v[i] = __expf(v[i] - mx); s += v[i]; }
#pragma unroll
    for (int o = 16; o > 0; o >>= 1) s += __shfl_xor_sync(0xffffffffu, s, o);
    if (lane == 0) shs[w] = s;
    __syncthreads();
    if (tid == 0) {
        float t = 0.f;
#pragma unroll
        for (int i = 0; i < 8; ++i) t += shs[i];
        shs[0] = t;
    }
    __syncthreads();
    const float inv = 1.f / shs[0];
#pragma unroll
    for (int i = 0; i < 16; ++i) {
        const __nv_bfloat162 h2 = __floats2bfloat162_rn(v[2 * i] * inv,
                                                        v[2 * i + 1] * inv);
        *reinterpret_cast<__nv_bfloat162*>(p + tid * 2 + (i << 9)) = h2;
    }
}

// row L2-normalize (D=1024) F -> accumulate into G
__global__ void norm_acc_kernel(const float* __restrict__ F, float* __restrict__ G,
                                int accumulate)
{
    const float* p = F + (size_t)blockIdx.x * 1024;
    float* q = G + (size_t)blockIdx.x * 1024;
    const int tid = threadIdx.x;
    const int lane = tid & 31, w = tid >> 5;

    const float4 v = *reinterpret_cast<const float4*>(p + tid * 4);
    float ss = v.x * v.x + v.y * v.y + v.z * v.z + v.w * v.w;
#pragma unroll
    for (int o = 16; o > 0; o >>= 1) ss += __shfl_xor_sync(0xffffffffu, ss, o);
    __shared__ float sh[8];
    if (lane == 0) sh[w] = ss;
    __syncthreads();
    if (tid == 0) {
        float t = 0.f;
#pragma unroll
        for (int i = 0; i < 8; ++i) t += sh[i];
        sh[0] = t;
    }
    __syncthreads();
    const float rn = rsqrtf(sh[0]);

    float4 o;
    if (accumulate) {
        const float4 g0 = *reinterpret_cast<const float4*>(q + tid * 4);
        o = make_float4(g0.x + v.x * rn, g0.y + v.y * rn,
                        g0.z + v.z * rn, g0.w + v.w * rn);
    } else {
        o = make_float4(v.x * rn, v.y * rn, v.z * rn, v.w * rn);
    }
    *reinterpret_cast<float4*>(q + tid * 4) = o;
}

// A' = [Gh | Gh | Gl]  (Bq x 3D)
__global__ void build_Ap_kernel(const float* __restrict__ G, bf16* __restrict__ Ap)
{
    const int idx = blockIdx.x * blockDim.x + threadIdx.x;
    if (idx >= Bq * Dq) return;
    const int r = idx >> 10, c = idx & 1023;
    const float v = G[idx];
    const bf16 h = __float2bfloat16(v);
    const bf16 l = __float2bfloat16(v - __bfloat162float(h));
    bf16* row = Ap + (size_t)r * 3072;
    row[c] = h; row[1024 + c] = h; row[2048 + c] = l;
}

// B' = [Fh | Fl | Fh]  (Cq x 3D)
__global__ void build_Bp_kernel(const float* __restrict__ Ft, bf16* __restrict__ Bp)
{
    const int idx = blockIdx.x * blockDim.x + threadIdx.x;
    if (idx >= Cq * Dq) return;
    const int r = idx >> 10, c = idx & 1023;
    const float v = Ft[idx];
    const bf16 h = __float2bfloat16(v);
    const bf16 l = __float2bfloat16(v - __bfloat162float(h));
    bf16* row = Bp + (size_t)r * 3072;
    row[c] = h; row[1024 + c] = l; row[2048 + c] = h;
}

// ---------------- host side ------------------------------------------------
static void tc(bool transB, const bf16* A, const bf16* B, int M, int N, int K,
               int mode, float scale,
               const float* bias, const float* gam, const float* bet,
               const float* mean, const float* var, const float* resid,
               const float* lsp, void* C, bf16* qo, bf16* ko, bf16* vo)
{
    if (!transB) {
        dim3 grid(N / 256, M / 128);
        tc_gemm<256, false><<<grid, 256, SMEM_NN256>>>(A, B, M, N, K, mode, scale,
            bias, gam, bet, mean, var, resid, lsp, C, qo, ko, vo);
    } else if (N >= 256) {
        dim3 grid((N + 255) / 256, M / 128);
        tc_gemm<256, true><<<grid, 256, SMEM_NT256>>>(A, B, M, N, K, mode, scale,
            bias, gam, bet, mean, var, resid, lsp, C, qo, ko, vo);
    } else {
        dim3 grid((N + 127) / 128, M / 128);
        tc_gemm<128, true><<<grid, 256, SMEM_NT128>>>(A, B, M, N, K, mode, scale,
            bias, gam, bet, mean, var, resid, lsp, C, qo, ko, vo);
    }
}

static void f2b(const float* in, bf16* out, int n)
{
    f2b_kernel<<<(n / 4 + 255) / 256, 256>>>(in, out, n);
}

extern "C" void kernel_launch(void* const* d_in, const int* in_sizes, int n_in,
                              void* d_out, int out_size)
{
    (void)in_sizes; (void)n_in; (void)out_size;
    const float* Ft  = (const float*)d_in[0];
    const float* Fv  = (const float*)d_in[1];
    const float* Fvs = (const float*)d_in[2];
    const float* Fvt = (const float*)d_in[3];
    const float* W1  = (const float*)d_in[4];
    const float* b1  = (const float*)d_in[5];
    const float* g1  = (const float*)d_in[6];
    const float* be1 = (const float*)d_in[7];
    const float* m1  = (const float*)d_in[8];
    const float* v1  = (const float*)d_in[9];
    const float* W2  = (const float*)d_in[10];
    const float* b2  = (const float*)d_in[11];
    const float* g2  = (const float*)d_in[12];
    const float* be2 = (const float*)d_in[13];
    const float* m2  = (const float*)d_in[14];
    const float* v2  = (const float*)d_in[15];
    const float* W3  = (const float*)d_in[16];
    const float* b3  = (const float*)d_in[17];
    const float* Wp  = (const float*)d_in[18];
    const float* bp  = (const float*)d_in[19];
    const float* ls  = (const float*)d_in[20];
    float* out = (float*)d_out;

    cudaFuncSetAttribute((const void*)tc_gemm<128, true>,
                         cudaFuncAttributeMaxDynamicSharedMemorySize, SMEM_NT128);
    cudaFuncSetAttribute((const void*)tc_gemm<256, true>,
                         cudaFuncAttributeMaxDynamicSharedMemorySize, SMEM_NT256);
    cudaFuncSetAttribute((const void*)tc_gemm<256, false>,
                         cudaFuncAttributeMaxDynamicSharedMemorySize, SMEM_NN256);

    bf16 *xb, *W1b, *W2b, *W3b, *Wpb, *H1b, *H2b, *Qb, *Kb, *Vb, *Sb, *AVb, *Ap, *Bp;
    float *F, *G;
    cudaGetSymbolAddress((void**)&xb,  g_xb);
    cudaGetSymbolAddress((void**)&W1b, g_W1b);
    cudaGetSymbolAddress((void**)&W2b, g_W2b);
    cudaGetSymbolAddress((void**)&W3b, g_W3b);
    cudaGetSymbolAddress((void**)&Wpb, g_Wpb);
    cudaGetSymbolAddress((void**)&H1b, g_H1b);
    cudaGetSymbolAddress((void**)&H2b, g_H2b);
    cudaGetSymbolAddress((void**)&Qb,  g_Qb);
    cudaGetSymbolAddress((void**)&Kb,  g_Kb);
    cudaGetSymbolAddress((void**)&Vb,  g_Vb);
    cudaGetSymbolAddress((void**)&Sb,  g_Sb);
    cudaGetSymbolAddress((void**)&AVb, g_AVb);
    cudaGetSymbolAddress((void**)&F,   g_F);
    cudaGetSymbolAddress((void**)&G,   g_G);
    cudaGetSymbolAddress((void**)&Ap,  g_Ap);
    cudaGetSymbolAddress((void**)&Bp,  g_Bp);

    // weight conversions (W3 row-permuted for grouped qkv epilogue)
    f2b(W1, W1b, Pq * Dq);
    f2b(W2, W2b, Pq * Pq);
    f2bW3_kernel<<<(3072 * 128 + 255) / 256, 256>>>(W3, W3b);
    f2b(Wp, Wpb, Dq * Dq);

    // ---- pre_project(Fv) -> Q ----
    f2b(Fv, xb, Bq * Dq);
    tc(true, xb,  W1b, Bq, Pq, Dq, MODE_BNRELU, 1.f, b1, g1, be1, m1, v1,
       nullptr, nullptr, H1b, nullptr, nullptr, nullptr);
    tc(true, H1b, W2b, Bq, Pq, Pq, MODE_BNRELU, 1.f, b2, g2, be2, m2, v2,
       nullptr, nullptr, H2b, nullptr, nullptr, nullptr);
    tc(true, H2b, W3b, Bq, 3 * Dq, Pq, MODE_QKV, 1.f, b3, nullptr, nullptr, nullptr,
       nullptr, nullptr, nullptr, nullptr, Qb, nullptr, nullptr);

    // ---- per bank ----
    for (int t = 0; t < 2; ++t) {
        const float* bank = t ? Fvt : Fvs;
        f2b(bank, xb, Nq * Dq);
        tc(true, xb,  W1b, Nq, Pq, Dq, MODE_BNRELU, 1.f, b1, g1, be1, m1, v1,
           nullptr, nullptr, H1b, nullptr, nullptr, nullptr);
        tc(true, H1b, W2b, Nq, Pq, Pq, MODE_BNRELU, 1.f, b2, g2, be2, m2, v2,
           nullptr, nullptr, H2b, nullptr, nullptr, nullptr);
        tc(true, H2b, W3b, Nq, 3 * Dq, Pq, MODE_QKV, 1.f, b3, nullptr, nullptr,
           nullptr, nullptr, nullptr, nullptr, nullptr, nullptr, Kb, Vb);

        // S = 0.1 * Q @ K^T   (bf16 out)
        tc(true, Qb, Kb, Bq, Nq, Dq, MODE_SMUL, 0.1f, nullptr, nullptr, nullptr,
           nullptr, nullptr, nullptr, nullptr, Sb, nullptr, nullptr, nullptr);
        softmax_bf16<<<Bq, 256>>>(Sb);

        // AV = S @ V  (NN: V is (K=8192, N=1024) row-major)
        tc(false, Sb, Vb, Bq, Dq, Nq, MODE_SMUL, 1.f, nullptr, nullptr, nullptr,
           nullptr, nullptr, nullptr, nullptr, AVb, nullptr, nullptr, nullptr);

        // F = Fv + AV @ Wp^T + bp   (fp32)
        tc(true, AVb, Wpb, Bq, Dq, Dq, MODE_RESID, 1.f, bp, nullptr, nullptr,
           nullptr, nullptr, Fv, nullptr, F, nullptr, nullptr, nullptr);

        norm_acc_kernel<<<Bq, 256>>>(F, G, t);
    }

    // ---- logits = exp(ls) * G @ Ft^T via bf16 split (3-term) ----
    build_Ap_kernel<<<(Bq * Dq + 255) / 256, 256>>>(G, Ap);
    build_Bp_kernel<<<(Cq * Dq + 255) / 256, 256>>>(Ft, Bp);
    tc(true, Ap, Bp, Bq, Cq, 3 * Dq, MODE_LS, 1.f, nullptr, nullptr, nullptr,
       nullptr, nullptr, nullptr, ls, out, nullptr, nullptr, nullptr);
}